// round 6
// baseline (speedup 1.0000x reference)
#include <cuda_runtime.h>
#include <cuda_bf16.h>
#include <cstdint>

#define T_LEN    8192
#define L_WIN    64
#define TP_LEN   (T_LEN - L_WIN + 1)   // 8129
#define P_NUM    64
#define BS       32
#define TILE_M   128
#define PAD_LEFT 32
#define EPS      1e-6f

// smem: A [128][72] bf16 (18432 B), B [64][72] bf16 (9216 B); fp32 staging
// (128 x 68 floats = 34816 B) overlays both after the MMA.
#define SA       72
#define SA_B     (SA * 2)               // 144 bytes per row
#define A_BYTES  (TILE_M * SA_B)        // 18432
#define B_BYTES  (P_NUM  * SA_B)        // 9216
#define STG_W    68
#define DYN_SMEM (TILE_M * STG_W * 4)   // 34816 (>= A_BYTES + B_BYTES)

union Pack8 { __nv_bfloat16 h[8]; uint4 u; };

__device__ __forceinline__ uint32_t smem_u32(const void* p) {
    uint32_t a;
    asm("{ .reg .u64 t; cvta.to.shared.u64 t, %1; cvt.u32.u64 %0, t; }"
        : "=r"(a) : "l"(p));
    return a;
}

__device__ __forceinline__ void ldsm_x4(uint32_t& r0, uint32_t& r1,
                                        uint32_t& r2, uint32_t& r3, uint32_t addr) {
    asm volatile("ldmatrix.sync.aligned.m8n8.x4.shared.b16 {%0,%1,%2,%3}, [%4];"
                 : "=r"(r0), "=r"(r1), "=r"(r2), "=r"(r3) : "r"(addr));
}

__device__ __forceinline__ void mma_16816_bf16(
    float* c, uint32_t a0, uint32_t a1, uint32_t a2, uint32_t a3,
    uint32_t b0, uint32_t b1)
{
    asm volatile(
        "mma.sync.aligned.m16n8k16.row.col.f32.bf16.bf16.f32 "
        "{%0,%1,%2,%3}, {%4,%5,%6,%7}, {%8,%9}, {%0,%1,%2,%3};"
        : "+f"(c[0]), "+f"(c[1]), "+f"(c[2]), "+f"(c[3])
        : "r"(a0), "r"(a1), "r"(a2), "r"(a3), "r"(b0), "r"(b1));
}

// ---------------------------------------------------------------------------
// Fused: 128 windows x 64 shapelets per CTA; pure-bf16 mma.sync (no hi/lo
// split — abs error << harness floor); z-norms folded into epilogue:
// act = exp(2*inv_t*dot_raw - w2_t - s2_p)
// ---------------------------------------------------------------------------
__global__ void __launch_bounds__(256)
shapelet_hmma2_kernel(const float* __restrict__ x,
                      const float* __restrict__ sh,
                      float* __restrict__ out)
{
    extern __shared__ char dyn[];
    __nv_bfloat16* As = reinterpret_cast<__nv_bfloat16*>(dyn);
    __nv_bfloat16* Bs = reinterpret_cast<__nv_bfloat16*>(dyn + A_BYTES);

    __shared__ float xs[TILE_M + L_WIN];   // 192
    __shared__ float invs[TILE_M];
    __shared__ float w2s[TILE_M];
    __shared__ float s2s[P_NUM];

    const int tid  = threadIdx.x;
    const int lane = tid & 31;
    const int wrp  = tid >> 5;             // 0..7
    const int b    = blockIdx.y;
    const int t0   = blockIdx.x * TILE_M;

    // ---- load raw x segment (zero past T) ----
    {
        const float* xb = x + (size_t)b * T_LEN;
        if (tid < TILE_M + L_WIN) {
            int i0 = t0 + tid;
            xs[tid] = (i0 < T_LEN) ? xb[i0] : 0.f;
        }
    }
    __syncthreads();

    // ---- per-window stats (threads 0..127) ----
    if (tid < TILE_M) {
        float s1 = 0.f, sq = 0.f;
        #pragma unroll
        for (int l = 0; l < L_WIN; l++) {
            float v = xs[tid + l];
            s1 += v; sq = fmaf(v, v, sq);
        }
        float mu  = s1 * (1.f / L_WIN);
        float var = fmaxf(sq * (1.f / L_WIN) - mu * mu, 0.f);
        float sd  = sqrtf(var);
        float inv = 1.f / fmaxf(sd, EPS);
        invs[tid] = inv;
        w2s[tid]  = var * inv * inv * (float)L_WIN;
    }

    // ---- A tile: row r = window, cols k = 0..63 = bf16(x[r+k]) ----
    {
        const int row = tid >> 1;
        const int c0  = (tid & 1) * 32;
        __nv_bfloat16* Arow = As + row * SA + c0;
        #pragma unroll
        for (int g = 0; g < 4; g++) {
            Pack8 pk;
            #pragma unroll
            for (int j = 0; j < 8; j++)
                pk.h[j] = __float2bfloat16(xs[row + c0 + g * 8 + j]);
            *reinterpret_cast<uint4*>(Arow + g * 8) = pk.u;
        }
    }

    // ---- shapelet z-norm + B tile (threads 0..63; row = shapelet p) ----
    if (tid < P_NUM) {
        const int p = tid;
        const float* row = sh + (size_t)p * L_WIN;
        float rv[L_WIN];
        float s1 = 0.f, sq = 0.f;
        #pragma unroll
        for (int l = 0; l < L_WIN; l++) {
            float v = row[l];
            rv[l] = v; s1 += v; sq = fmaf(v, v, sq);
        }
        float mu  = s1 * (1.f / L_WIN);
        float var = fmaxf(sq * (1.f / L_WIN) - mu * mu, 0.f);
        float sd  = sqrtf(var);
        float inv = 1.f / fmaxf(sd, EPS);
        float s2  = 0.f;
        __nv_bfloat16* Brow = Bs + p * SA;
        #pragma unroll
        for (int g = 0; g < 8; g++) {
            Pack8 pk;
            #pragma unroll
            for (int j = 0; j < 8; j++) {
                float sn = (rv[g * 8 + j] - mu) * inv;
                s2 = fmaf(sn, sn, s2);
                pk.h[j] = __float2bfloat16(sn);
            }
            *reinterpret_cast<uint4*>(Brow + g * 8) = pk.u;
        }
        s2s[p] = s2;
    }
    __syncthreads();

    // ---- MMA mainloop: warp owns rows [16*wrp, 16*wrp+16) ----
    const int rr = lane & 7;
    const int q  = lane >> 3;

    const uint32_t Au = smem_u32(As);
    const uint32_t Bu = Au + A_BYTES;
    // A ldmatrix.x4 quadrants: m0 rows+0 c0 | m1 rows+8 c0 | m2 rows+0 c8 | m3 rows+8 c8
    const uint32_t aAddr = Au + (uint32_t)(wrp * 16 + rr + (q & 1) * 8) * SA_B
                              + (uint32_t)(q >> 1) * 16;
    // B ldmatrix.x4 quadrants: m0 n+0 k0 | m1 n+0 k8 | m2 n+8 k0 | m3 n+8 k8
    const uint32_t bAddr = Bu + (uint32_t)(rr + (q >> 1) * 8) * SA_B
                              + (uint32_t)(q & 1) * 16;

    float c[8][4];
    #pragma unroll
    for (int nt = 0; nt < 8; nt++)
        #pragma unroll
        for (int r = 0; r < 4; r++) c[nt][r] = 0.f;

    #pragma unroll
    for (int k = 0; k < 4; k++) {
        uint32_t a0, a1, a2, a3;
        ldsm_x4(a0, a1, a2, a3, aAddr + (uint32_t)k * 32);
        #pragma unroll
        for (int nt2 = 0; nt2 < 4; nt2++) {
            uint32_t b0, b1, b2, b3;
            ldsm_x4(b0, b1, b2, b3, bAddr + (uint32_t)nt2 * (16 * SA_B) + (uint32_t)k * 32);
            mma_16816_bf16(c[2 * nt2],     a0, a1, a2, a3, b0, b1);
            mma_16816_bf16(c[2 * nt2 + 1], a0, a1, a2, a3, b2, b3);
        }
    }
    __syncthreads();   // done with As/Bs; region becomes fp32 staging

    // ---- epilogue: act = exp(2*inv*dot - w2 - s2[p]) -> staged fp32 ----
    {
        float* stg = reinterpret_cast<float*>(dyn);
        const int g  = lane >> 2;
        const int tq = lane & 3;
        #pragma unroll
        for (int half = 0; half < 2; half++) {
            const int rowL = wrp * 16 + g + half * 8;
            const int t    = t0 + rowL;
            const bool ok  = (t < TP_LEN);
            const float inv2 = 2.f * invs[rowL];
            const float cw   = w2s[rowL];
            #pragma unroll
            for (int nt = 0; nt < 8; nt++) {
                const int col = nt * 8 + tq * 2;
                float2 v;
                v.x = ok ? __expf(fmaf(inv2, c[nt][half * 2 + 0], -(cw + s2s[col])))     : 0.f;
                v.y = ok ? __expf(fmaf(inv2, c[nt][half * 2 + 1], -(cw + s2s[col + 1]))) : 0.f;
                *reinterpret_cast<float2*>(stg + rowL * STG_W + col) = v;
            }
        }
    }
    __syncthreads();

    // ---- coalesced store: 128 rows x 64 floats ----
    {
        float* outb = out + (size_t)b * T_LEN * P_NUM;
        const float* stg = reinterpret_cast<const float*>(dyn);
        #pragma unroll
        for (int it = 0; it < 8; it++) {
            int qq   = tid + it * 256;
            int row  = qq >> 4;
            int c4   = qq & 15;
            int tout = t0 + row + PAD_LEFT;
            if (tout < T_LEN) {
                float4 v = *reinterpret_cast<const float4*>(stg + row * STG_W + c4 * 4);
                *reinterpret_cast<float4*>(outb + (size_t)tout * P_NUM + c4 * 4) = v;
            }
        }
        // left pad rows [0,32): zeros (tile 0 only)
        if (blockIdx.x == 0) {
            float4 z = make_float4(0.f, 0.f, 0.f, 0.f);
            #pragma unroll
            for (int it = 0; it < 2; it++) {
                int qq  = tid + it * 256;
                int row = qq >> 4;
                int c4  = qq & 15;
                *reinterpret_cast<float4*>(outb + (size_t)row * P_NUM + c4 * 4) = z;
            }
        }
    }
}

extern "C" void kernel_launch(void* const* d_in, const int* in_sizes, int n_in,
                              void* d_out, int out_size) {
    const float* x  = (const float*)d_in[0];   // (32, 8192, 1)
    const float* sh = (const float*)d_in[1];   // (64, 1, 64)
    float* out = (float*)d_out;                // (32, 8192, 64)

    cudaFuncSetAttribute(shapelet_hmma2_kernel,
                         cudaFuncAttributeMaxDynamicSharedMemorySize, DYN_SMEM);
    dim3 grid((TP_LEN + TILE_M - 1) / TILE_M, BS);   // (64, 32)
    shapelet_hmma2_kernel<<<grid, 256, DYN_SMEM>>>(x, sh, out);
}

// round 7
// speedup vs baseline: 2.9195x; 2.9195x over previous
#include <cuda_runtime.h>
#include <cuda_bf16.h>
#include <cstdint>

#define T_LEN    8192
#define L_WIN    64
#define TP_LEN   (T_LEN - L_WIN + 1)   // 8129
#define P_NUM    64
#define BS       32
#define TILE_M   128
#define PAD_LEFT 32
#define EPS      1e-6f

// dynamic smem: A [128][72] bf16, B [64][72] bf16, shs raw floats [64][64]
#define SA       72
#define SA_B     (SA * 2)                 // 144 B per row
#define A_BYTES  (TILE_M * SA_B)          // 18432
#define B_BYTES  (P_NUM  * SA_B)          // 9216
#define SHS_OFF  (A_BYTES + B_BYTES)      // 27648
#define DYN_SMEM (SHS_OFF + P_NUM * L_WIN * 4)   // 27648 + 16384 = 44032

union Pack8 { __nv_bfloat16 h[8]; uint4 u; };

__device__ __forceinline__ uint32_t smem_u32(const void* p) {
    uint32_t a;
    asm("{ .reg .u64 t; cvta.to.shared.u64 t, %1; cvt.u32.u64 %0, t; }"
        : "=r"(a) : "l"(p));
    return a;
}

__device__ __forceinline__ void ldsm_x4(uint32_t& r0, uint32_t& r1,
                                        uint32_t& r2, uint32_t& r3, uint32_t addr) {
    asm volatile("ldmatrix.sync.aligned.m8n8.x4.shared.b16 {%0,%1,%2,%3}, [%4];"
                 : "=r"(r0), "=r"(r1), "=r"(r2), "=r"(r3) : "r"(addr));
}

__device__ __forceinline__ void mma_16816_bf16(
    float* c, uint32_t a0, uint32_t a1, uint32_t a2, uint32_t a3,
    uint32_t b0, uint32_t b1)
{
    asm volatile(
        "mma.sync.aligned.m16n8k16.row.col.f32.bf16.bf16.f32 "
        "{%0,%1,%2,%3}, {%4,%5,%6,%7}, {%8,%9}, {%0,%1,%2,%3};"
        : "+f"(c[0]), "+f"(c[1]), "+f"(c[2]), "+f"(c[3])
        : "r"(a0), "r"(a1), "r"(a2), "r"(a3), "r"(b0), "r"(b1));
}

// ---------------------------------------------------------------------------
// 128 windows x 64 shapelets per CTA; pure-bf16 mma.sync; z-norms folded:
// act = exp(2*inv_t*dot_raw - w2_t - s2_p). Direct-STG epilogue.
// ---------------------------------------------------------------------------
__global__ void __launch_bounds__(256)
shapelet_hmma3_kernel(const float* __restrict__ x,
                      const float* __restrict__ sh,
                      float* __restrict__ out)
{
    extern __shared__ char dyn[];
    __nv_bfloat16* As = reinterpret_cast<__nv_bfloat16*>(dyn);
    __nv_bfloat16* Bs = reinterpret_cast<__nv_bfloat16*>(dyn + A_BYTES);
    float*        shs = reinterpret_cast<float*>(dyn + SHS_OFF);

    __shared__ float xs[TILE_M + L_WIN];   // 192
    __shared__ float invs[TILE_M];
    __shared__ float w2s[TILE_M];
    __shared__ float s2s[P_NUM];

    const int tid  = threadIdx.x;
    const int lane = tid & 31;
    const int wrp  = tid >> 5;             // 0..7
    const int b    = blockIdx.y;
    const int t0   = blockIdx.x * TILE_M;

    // ---- coalesced loads: x segment + full shapelet table ----
    {
        const float* xb = x + (size_t)b * T_LEN;
        if (tid < TILE_M + L_WIN) {
            int i0 = t0 + tid;
            xs[tid] = (i0 < T_LEN) ? xb[i0] : 0.f;
        }
        const float4* sh4 = reinterpret_cast<const float4*>(sh);
        float4*       ss4 = reinterpret_cast<float4*>(shs);
        #pragma unroll
        for (int i = 0; i < 4; i++)
            ss4[tid + i * 256] = sh4[tid + i * 256];
    }
    __syncthreads();

    // ---- per-window stats (threads 0..127) ----
    if (tid < TILE_M) {
        float s1 = 0.f, sq = 0.f;
        #pragma unroll
        for (int l = 0; l < L_WIN; l++) {
            float v = xs[tid + l];
            s1 += v; sq = fmaf(v, v, sq);
        }
        float mu  = s1 * (1.f / L_WIN);
        float var = fmaxf(sq * (1.f / L_WIN) - mu * mu, 0.f);
        float inv = 1.f / fmaxf(sqrtf(var), EPS);
        invs[tid] = inv;
        w2s[tid]  = var * inv * inv * (float)L_WIN;
    }

    // ---- A tile: row r = window, cols k = bf16(x[r+k]) ----
    {
        const int row = tid >> 1;
        const int c0  = (tid & 1) * 32;
        __nv_bfloat16* Arow = As + row * SA + c0;
        #pragma unroll
        for (int g = 0; g < 4; g++) {
            Pack8 pk;
            #pragma unroll
            for (int j = 0; j < 8; j++)
                pk.h[j] = __float2bfloat16(xs[row + c0 + g * 8 + j]);
            *reinterpret_cast<uint4*>(Arow + g * 8) = pk.u;
        }
    }

    // ---- shapelet z-norm: warp w -> rows 8w..8w+7, shuffle reduction ----
    {
        #pragma unroll
        for (int i = 0; i < 8; i++) {
            const int r = wrp * 8 + i;
            float v0 = shs[r * 64 + lane];
            float v1 = shs[r * 64 + lane + 32];
            float s1 = v0 + v1;
            float sq = fmaf(v0, v0, v1 * v1);
            #pragma unroll
            for (int m = 16; m > 0; m >>= 1) {
                s1 += __shfl_xor_sync(0xffffffffu, s1, m);
                sq += __shfl_xor_sync(0xffffffffu, sq, m);
            }
            float mu  = s1 * (1.f / L_WIN);
            float var = fmaxf(sq * (1.f / L_WIN) - mu * mu, 0.f);
            float inv = 1.f / fmaxf(sqrtf(var), EPS);
            Bs[r * SA + lane]      = __float2bfloat16((v0 - mu) * inv);
            Bs[r * SA + lane + 32] = __float2bfloat16((v1 - mu) * inv);
            if (lane == 0) s2s[r] = var * inv * inv * (float)L_WIN;
        }
    }
    __syncthreads();

    // ---- MMA mainloop: warp owns rows [16*wrp, 16*wrp+16), K=64 ----
    const int rr = lane & 7;
    const int q  = lane >> 3;

    const uint32_t Au = smem_u32(As);
    const uint32_t Bu = Au + A_BYTES;
    const uint32_t aAddr = Au + (uint32_t)(wrp * 16 + rr + (q & 1) * 8) * SA_B
                              + (uint32_t)(q >> 1) * 16;
    const uint32_t bAddr = Bu + (uint32_t)(rr + (q >> 1) * 8) * SA_B
                              + (uint32_t)(q & 1) * 16;

    float c[8][4];
    #pragma unroll
    for (int nt = 0; nt < 8; nt++)
        #pragma unroll
        for (int r = 0; r < 4; r++) c[nt][r] = 0.f;

    #pragma unroll
    for (int k = 0; k < 4; k++) {
        uint32_t a0, a1, a2, a3;
        ldsm_x4(a0, a1, a2, a3, aAddr + (uint32_t)k * 32);
        #pragma unroll
        for (int nt2 = 0; nt2 < 4; nt2++) {
            uint32_t b0, b1, b2, b3;
            ldsm_x4(b0, b1, b2, b3, bAddr + (uint32_t)nt2 * (16 * SA_B) + (uint32_t)k * 32);
            mma_16816_bf16(c[2 * nt2],     a0, a1, a2, a3, b0, b1);
            mma_16816_bf16(c[2 * nt2 + 1], a0, a1, a2, a3, b2, b3);
        }
    }

    // ---- epilogue: direct STG from fragments ----
    // c[nt][half*2 + r] -> row = wrp*16 + g + half*8, col = nt*8 + tq*2 + r
    {
        float* outb = out + (size_t)b * T_LEN * P_NUM;
        const int g  = lane >> 2;
        const int tq = lane & 3;
        #pragma unroll
        for (int half = 0; half < 2; half++) {
            const int rowL = wrp * 16 + g + half * 8;
            const int t    = t0 + rowL;
            const int tout = t + PAD_LEFT;
            if (tout < T_LEN) {
                const bool ok  = (t < TP_LEN);
                const float inv2 = 2.f * invs[rowL];
                const float cw   = w2s[rowL];
                float* orow = outb + (size_t)tout * P_NUM;
                #pragma unroll
                for (int nt = 0; nt < 8; nt++) {
                    const int col = nt * 8 + tq * 2;
                    float2 v;
                    v.x = ok ? __expf(fmaf(inv2, c[nt][half * 2 + 0], -(cw + s2s[col])))     : 0.f;
                    v.y = ok ? __expf(fmaf(inv2, c[nt][half * 2 + 1], -(cw + s2s[col + 1]))) : 0.f;
                    *reinterpret_cast<float2*>(orow + col) = v;
                }
            }
        }
        // left pad rows [0,32): zeros (tile 0 only)
        if (blockIdx.x == 0) {
            float4 z = make_float4(0.f, 0.f, 0.f, 0.f);
            #pragma unroll
            for (int it = 0; it < 2; it++) {
                int qq  = tid + it * 256;
                int row = qq >> 4;
                int c4  = qq & 15;
                *reinterpret_cast<float4*>(outb + (size_t)row * P_NUM + c4 * 4) = z;
            }
        }
    }
}

extern "C" void kernel_launch(void* const* d_in, const int* in_sizes, int n_in,
                              void* d_out, int out_size) {
    const float* x  = (const float*)d_in[0];   // (32, 8192, 1)
    const float* sh = (const float*)d_in[1];   // (64, 1, 64)
    float* out = (float*)d_out;                // (32, 8192, 64)

    cudaFuncSetAttribute(shapelet_hmma3_kernel,
                         cudaFuncAttributeMaxDynamicSharedMemorySize, DYN_SMEM);
    dim3 grid((TP_LEN + TILE_M - 1) / TILE_M, BS);   // (64, 32)
    shapelet_hmma3_kernel<<<grid, 256, DYN_SMEM>>>(x, sh, out);
}